// round 6
// baseline (speedup 1.0000x reference)
#include <cuda_runtime.h>
#include <stdint.h>

#define NPIX  200704        // 64 * 56 * 56
#define HW    3136          // 56 * 56
#define WID   56
#define NTHR4 (NPIX / 4)    // kA: 50176 threads, 4 pixels each
#define NTHR8 (NPIX / 8)    // kB: 25088 threads, 8 pixels each

// Intermediate: 32 sign bits (channels of h) per pixel, layout [b*HW + s]
__device__ uint32_t g_a[NPIX];

// ---------------------------------------------------------------------------
// Kernel A: x [N=64, C=64, 56, 56] (NCHW) -> g_a sign masks.
// Self-contained: packs w1 + folds BN1 per block (ballot), then 4 px/thread.
// ---------------------------------------------------------------------------
__global__ __launch_bounds__(256) void kA(const float* __restrict__ x,
                                          const float* __restrict__ w1,
                                          const float* __restrict__ g1,
                                          const float* __restrict__ b1,
                                          const float* __restrict__ m1,
                                          const float* __restrict__ v1)
{
    __shared__ unsigned long long sw1[32];
    __shared__ float sinv[32], ssh[32];

    const int wid8 = threadIdx.x >> 5;
    const int lane = threadIdx.x & 31;

    // pack w1: warp w packs channels w, w+8, w+16, w+24
#pragma unroll
    for (int o = wid8; o < 32; o += 8) {
        float lo = w1[o * 64 + lane];
        float hi = w1[o * 64 + 32 + lane];
        uint32_t blo = __ballot_sync(0xffffffffu, lo > 0.0f);
        uint32_t bhi = __ballot_sync(0xffffffffu, hi > 0.0f);
        if (lane == 0)
            sw1[o] = (unsigned long long)blo | ((unsigned long long)bhi << 32);
    }
    if (threadIdx.x < 32) {
        int o = threadIdx.x;
        float inv = g1[o] * rsqrtf(v1[o] + 1e-5f);
        sinv[o] = inv;
        ssh[o]  = b1[o] - m1[o] * inv;
    }
    __syncthreads();

    int t = blockIdx.x * 256 + threadIdx.x;
    if (t >= NTHR4) return;
    int p = t * 4;                 // global pixel index = b*HW + s
    int b = p / HW;
    int s = p - b * HW;
    const float* xb = x + (size_t)b * 64 * HW + s;

    unsigned long long xb0 = 0, xb1 = 0, xb2 = 0, xb3 = 0;
#pragma unroll
    for (int c = 0; c < 64; c++) {
        float4 v = __ldg((const float4*)(xb + (size_t)c * HW));
        unsigned long long m = 1ull << c;
        if (v.x > 0.0f) xb0 |= m;
        if (v.y > 0.0f) xb1 |= m;
        if (v.z > 0.0f) xb2 |= m;
        if (v.w > 0.0f) xb3 |= m;
    }

    uint32_t a0 = 0, a1 = 0, a2 = 0, a3 = 0;
#pragma unroll
    for (int o = 0; o < 32; o++) {
        unsigned long long wb = sw1[o];
        float inv = sinv[o], sh = ssh[o];
        uint32_t m = 1u << o;
        int d0 = 64 - 2 * __popcll(xb0 ^ wb);
        int d1 = 64 - 2 * __popcll(xb1 ^ wb);
        int d2 = 64 - 2 * __popcll(xb2 ^ wb);
        int d3 = 64 - 2 * __popcll(xb3 ^ wb);
        if (fmaf((float)d0, inv, sh) > 0.0f) a0 |= m;
        if (fmaf((float)d1, inv, sh) > 0.0f) a1 |= m;
        if (fmaf((float)d2, inv, sh) > 0.0f) a2 |= m;
        if (fmaf((float)d3, inv, sh) > 0.0f) a3 |= m;
    }
    *(uint4*)(g_a + p) = make_uint4(a0, a1, a2, a3);
}

// ---------------------------------------------------------------------------
// Kernel B: g_a -> output [64,256,56,56]. Self-contained prep (ballot packing
// + BN fold into smem), 8 pixels/thread, LDS.128-packed weight tables.
// smem layout per channel: sV/sH = uint4{w0,w1,w2,inv_bits}; sP = {w,inv,sh,0}
// ---------------------------------------------------------------------------
__global__ __launch_bounds__(128) void kB(
    const float* __restrict__ w2, const float* __restrict__ g2,
    const float* __restrict__ b2, const float* __restrict__ m2,
    const float* __restrict__ v2,
    const float* __restrict__ w3, const float* __restrict__ g3,
    const float* __restrict__ b3, const float* __restrict__ m3,
    const float* __restrict__ v3,
    const float* __restrict__ w4, const float* __restrict__ g4,
    const float* __restrict__ b4, const float* __restrict__ m4,
    const float* __restrict__ v4,
    float* __restrict__ out)
{
    __shared__ __align__(16) uint32_t sV[96 * 4];
    __shared__ __align__(16) uint32_t sH[96 * 4];
    __shared__ __align__(16) uint32_t sP[64 * 4];
    __shared__ float sVsh[96], sHsh[96];

    const int t    = threadIdx.x;
    const int wrp  = t >> 5;     // 0..3
    const int lane = t & 31;

    // ---- ballot-pack w2/w3 (96 ch x 3 taps) and w4 (64 ch)
    for (int o = wrp; o < 96; o += 4) {
        const float* p2 = w2 + (o * 32 + lane) * 3;
        const float* p3 = w3 + (o * 32 + lane) * 3;
        float a0 = p2[0], a1 = p2[1], a2 = p2[2];
        float c0 = p3[0], c1 = p3[1], c2 = p3[2];
        uint32_t x0 = __ballot_sync(0xffffffffu, a0 > 0.0f);
        uint32_t x1 = __ballot_sync(0xffffffffu, a1 > 0.0f);
        uint32_t x2 = __ballot_sync(0xffffffffu, a2 > 0.0f);
        uint32_t y0 = __ballot_sync(0xffffffffu, c0 > 0.0f);
        uint32_t y1 = __ballot_sync(0xffffffffu, c1 > 0.0f);
        uint32_t y2 = __ballot_sync(0xffffffffu, c2 > 0.0f);
        if (lane == 0) {
            sV[4 * o] = x0; sV[4 * o + 1] = x1; sV[4 * o + 2] = x2;
            sH[4 * o] = y0; sH[4 * o + 1] = y1; sH[4 * o + 2] = y2;
        }
    }
    for (int o = wrp; o < 64; o += 4) {
        uint32_t p = __ballot_sync(0xffffffffu, w4[o * 32 + lane] > 0.0f);
        if (lane == 0) sP[4 * o] = p;
    }
    // ---- BN fold
    if (t < 96) {
        float inv = g2[t] * rsqrtf(v2[t] + 1e-5f);
        sV[4 * t + 3] = __float_as_uint(inv);
        sVsh[t] = b2[t] - m2[t] * inv;
        float inv3 = g3[t] * rsqrtf(v3[t] + 1e-5f);
        sH[4 * t + 3] = __float_as_uint(inv3);
        sHsh[t] = b3[t] - m3[t] * inv3;
    }
    if (t < 64) {
        float inv = g4[t] * rsqrtf(v4[t] + 1e-5f);
        sP[4 * t + 1] = __float_as_uint(inv);
        sP[4 * t + 2] = __float_as_uint(b4[t] - m4[t] * inv);
        sP[4 * t + 3] = 0u;
    }
    __syncthreads();

    // ---- pixel group: 8 consecutive pixels along a row
    int q  = blockIdx.x * 128 + t;           // 0..25087
    int bb = q / 392;                        // image (HW/8 = 392 groups)
    int g  = q - bb * 392;
    int y  = g / 7;
    int xq = g - y * 7;                      // 0..6
    int pix = bb * HW + g * 8;               // == q*8

    uint32_t C[8], U[8], D[8];
    {
        uint4 v0 = *(const uint4*)&g_a[pix];
        uint4 v1 = *(const uint4*)&g_a[pix + 4];
        C[0]=v0.x; C[1]=v0.y; C[2]=v0.z; C[3]=v0.w;
        C[4]=v1.x; C[5]=v1.y; C[6]=v1.z; C[7]=v1.w;
    }
    if (y > 0) {
        uint4 v0 = *(const uint4*)&g_a[pix - WID];
        uint4 v1 = *(const uint4*)&g_a[pix - WID + 4];
        U[0]=v0.x; U[1]=v0.y; U[2]=v0.z; U[3]=v0.w;
        U[4]=v1.x; U[5]=v1.y; U[6]=v1.z; U[7]=v1.w;
    } else {
#pragma unroll
        for (int i = 0; i < 8; i++) U[i] = 0u;
    }
    if (y < 55) {
        uint4 v0 = *(const uint4*)&g_a[pix + WID];
        uint4 v1 = *(const uint4*)&g_a[pix + WID + 4];
        D[0]=v0.x; D[1]=v0.y; D[2]=v0.z; D[3]=v0.w;
        D[4]=v1.x; D[5]=v1.y; D[6]=v1.z; D[7]=v1.w;
    } else {
#pragma unroll
        for (int i = 0; i < 8; i++) D[i] = 0u;
    }
    uint32_t hL = (xq > 0) ? g_a[pix - 1] : 0u;
    uint32_t hR = (xq < 6) ? g_a[pix + 8] : 0u;

    uint32_t L[8], R[8];
    L[0] = hL; R[7] = hR;
#pragma unroll
    for (int i = 1; i < 8; i++) L[i] = C[i - 1];
#pragma unroll
    for (int i = 0; i < 7; i++) R[i] = C[i + 1];

    int pc[8], pv[8], ph[8];
#pragma unroll
    for (int i = 0; i < 8; i++) pc[i] = __popc(C[i]);
#pragma unroll
    for (int i = 0; i < 8; i++) pv[i] = __popc(U[i]) + pc[i] + __popc(D[i]);
    {
        int pl = __popc(hL), pr = __popc(hR);
        ph[0] = pl + pc[0] + pc[1];
#pragma unroll
        for (int i = 1; i < 7; i++) ph[i] = pc[i - 1] + pc[i] + pc[i + 1];
        ph[7] = pc[6] + pc[7] + pr;
    }

    float* o1 = out + (size_t)bb * 256 * HW + g * 8;

    // ---- Branch 1: 3x1 vertical conv (out channels 0..95)
#pragma unroll 2
    for (int o = 0; o < 96; o++) {
        uint4 wv = *(const uint4*)&sV[4 * o];
        float inv = __uint_as_float(wv.w);
        float sh  = sVsh[o];
        float r[8];
#pragma unroll
        for (int i = 0; i < 8; i++) {
            int d = 2 * (__popc(U[i] & wv.x) + __popc(C[i] & wv.y) +
                         __popc(D[i] & wv.z)) - pv[i];
            r[i] = fmaxf(fmaf((float)d, inv, sh), 0.0f);
        }
        float* po = o1 + (size_t)o * HW;
        *(float4*)po       = make_float4(r[0], r[1], r[2], r[3]);
        *(float4*)(po + 4) = make_float4(r[4], r[5], r[6], r[7]);
    }

    // ---- Branch 2: 1x3 horizontal conv (out channels 96..191)
    float* o2 = o1 + (size_t)96 * HW;
#pragma unroll 2
    for (int o = 0; o < 96; o++) {
        uint4 wv = *(const uint4*)&sH[4 * o];
        float inv = __uint_as_float(wv.w);
        float sh  = sHsh[o];
        float r[8];
#pragma unroll
        for (int i = 0; i < 8; i++) {
            int d = 2 * (__popc(L[i] & wv.x) + __popc(C[i] & wv.y) +
                         __popc(R[i] & wv.z)) - ph[i];
            r[i] = fmaxf(fmaf((float)d, inv, sh), 0.0f);
        }
        float* po = o2 + (size_t)o * HW;
        *(float4*)po       = make_float4(r[0], r[1], r[2], r[3]);
        *(float4*)(po + 4) = make_float4(r[4], r[5], r[6], r[7]);
    }

    // ---- Branch 3: 1x1 conv (out channels 192..255)
    float* o3 = o1 + (size_t)192 * HW;
#pragma unroll 2
    for (int o = 0; o < 64; o++) {
        uint4 wv = *(const uint4*)&sP[4 * o];
        float inv = __uint_as_float(wv.y);
        float sh  = __uint_as_float(wv.z);
        float r[8];
#pragma unroll
        for (int i = 0; i < 8; i++) {
            int d = 2 * __popc(C[i] & wv.x) - pc[i];
            r[i] = fmaxf(fmaf((float)d, inv, sh), 0.0f);
        }
        float* po = o3 + (size_t)o * HW;
        *(float4*)po       = make_float4(r[0], r[1], r[2], r[3]);
        *(float4*)(po + 4) = make_float4(r[4], r[5], r[6], r[7]);
    }
}

// ---------------------------------------------------------------------------
extern "C" void kernel_launch(void* const* d_in, const int* in_sizes, int n_in,
                              void* d_out, int out_size)
{
    const float* x = (const float*)d_in[0];
    kA<<<NTHR4 / 256, 256>>>(x,
                             (const float*)d_in[1], (const float*)d_in[2],
                             (const float*)d_in[3], (const float*)d_in[4],
                             (const float*)d_in[5]);
    kB<<<NTHR8 / 128, 128>>>(
        (const float*)d_in[6],  (const float*)d_in[7],
        (const float*)d_in[8],  (const float*)d_in[9],
        (const float*)d_in[10],
        (const float*)d_in[11], (const float*)d_in[12],
        (const float*)d_in[13], (const float*)d_in[14],
        (const float*)d_in[15],
        (const float*)d_in[16], (const float*)d_in[17],
        (const float*)d_in[18], (const float*)d_in[19],
        (const float*)d_in[20],
        (float*)d_out);
}

// round 7
// speedup vs baseline: 1.6572x; 1.6572x over previous
#include <cuda_runtime.h>
#include <stdint.h>

#define NPIX  200704        // 64 * 56 * 56
#define HW    3136          // 56 * 56
#define WID   56
#define NTHR4 (NPIX / 4)    // 50176 threads, 4 pixels each

// Intermediate: 32 sign bits (channels of h) per pixel, layout [b*HW + s]
__device__ uint32_t g_a[NPIX];

// ---------------------------------------------------------------------------
// Kernel A: x [N=64, C=64, 56, 56] (NCHW) -> g_a sign masks.
// Self-contained: packs w1 + folds BN1 per block (ballot), then 4 px/thread.
// ---------------------------------------------------------------------------
__global__ __launch_bounds__(256) void kA(const float* __restrict__ x,
                                          const float* __restrict__ w1,
                                          const float* __restrict__ g1,
                                          const float* __restrict__ b1,
                                          const float* __restrict__ m1,
                                          const float* __restrict__ v1)
{
    __shared__ unsigned long long sw1[32];
    __shared__ float sinv[32], ssh[32];

    const int wid8 = threadIdx.x >> 5;
    const int lane = threadIdx.x & 31;

#pragma unroll
    for (int o = wid8; o < 32; o += 8) {
        float lo = w1[o * 64 + lane];
        float hi = w1[o * 64 + 32 + lane];
        uint32_t blo = __ballot_sync(0xffffffffu, lo > 0.0f);
        uint32_t bhi = __ballot_sync(0xffffffffu, hi > 0.0f);
        if (lane == 0)
            sw1[o] = (unsigned long long)blo | ((unsigned long long)bhi << 32);
    }
    if (threadIdx.x < 32) {
        int o = threadIdx.x;
        float inv = g1[o] * rsqrtf(v1[o] + 1e-5f);
        sinv[o] = inv;
        ssh[o]  = b1[o] - m1[o] * inv;
    }
    __syncthreads();

    int t = blockIdx.x * 256 + threadIdx.x;
    if (t >= NTHR4) return;
    int p = t * 4;
    int b = p / HW;
    int s = p - b * HW;
    const float* xb = x + (size_t)b * 64 * HW + s;

    unsigned long long xb0 = 0, xb1 = 0, xb2 = 0, xb3 = 0;
#pragma unroll
    for (int c = 0; c < 64; c++) {
        float4 v = __ldg((const float4*)(xb + (size_t)c * HW));
        unsigned long long m = 1ull << c;
        if (v.x > 0.0f) xb0 |= m;
        if (v.y > 0.0f) xb1 |= m;
        if (v.z > 0.0f) xb2 |= m;
        if (v.w > 0.0f) xb3 |= m;
    }

    uint32_t a0 = 0, a1 = 0, a2 = 0, a3 = 0;
#pragma unroll
    for (int o = 0; o < 32; o++) {
        unsigned long long wb = sw1[o];
        float inv = sinv[o], sh = ssh[o];
        uint32_t m = 1u << o;
        int d0 = 64 - 2 * __popcll(xb0 ^ wb);
        int d1 = 64 - 2 * __popcll(xb1 ^ wb);
        int d2 = 64 - 2 * __popcll(xb2 ^ wb);
        int d3 = 64 - 2 * __popcll(xb3 ^ wb);
        if (fmaf((float)d0, inv, sh) > 0.0f) a0 |= m;
        if (fmaf((float)d1, inv, sh) > 0.0f) a1 |= m;
        if (fmaf((float)d2, inv, sh) > 0.0f) a2 |= m;
        if (fmaf((float)d3, inv, sh) > 0.0f) a3 |= m;
    }
    *(uint4*)(g_a + p) = make_uint4(a0, a1, a2, a3);
}

// ---------------------------------------------------------------------------
// Kernel B: g_a -> output [64,256,56,56].
// Grid (196, 8): blockIdx.x = pixel tile (256 threads x 4 px),
// blockIdx.y = 32-channel group: 0-2 = branch V (w2), 3-5 = branch H (w3),
// 6-7 = branch P (w4). Per-block ballot prep of just its 32 channels.
// smem per channel: uint4{w0,w1,w2,inv_bits} (+ sh for V/H; P packs sh in w2 slot).
// ---------------------------------------------------------------------------
__global__ __launch_bounds__(256) void kB(
    const float* __restrict__ w2, const float* __restrict__ g2,
    const float* __restrict__ b2, const float* __restrict__ m2,
    const float* __restrict__ v2,
    const float* __restrict__ w3, const float* __restrict__ g3,
    const float* __restrict__ b3, const float* __restrict__ m3,
    const float* __restrict__ v3,
    const float* __restrict__ w4, const float* __restrict__ g4,
    const float* __restrict__ b4, const float* __restrict__ m4,
    const float* __restrict__ v4,
    float* __restrict__ out)
{
    __shared__ __align__(16) uint32_t sw[32 * 4];
    __shared__ float ssh[32];

    const int grp  = blockIdx.y;        // 0..7
    const int wrp  = threadIdx.x >> 5;  // 0..7
    const int lane = threadIdx.x & 31;

    // ---- per-block prep: 32 channels only
    if (grp < 6) {
        const float* wsrc = (grp < 3) ? w2 : w3;
        const int base = (grp < 3 ? grp : grp - 3) * 32;
#pragma unroll
        for (int o = wrp; o < 32; o += 8) {
            const float* pw = wsrc + ((base + o) * 32 + lane) * 3;
            float a0 = pw[0], a1 = pw[1], a2 = pw[2];
            uint32_t x0 = __ballot_sync(0xffffffffu, a0 > 0.0f);
            uint32_t x1 = __ballot_sync(0xffffffffu, a1 > 0.0f);
            uint32_t x2 = __ballot_sync(0xffffffffu, a2 > 0.0f);
            if (lane == 0) {
                sw[4 * o] = x0; sw[4 * o + 1] = x1; sw[4 * o + 2] = x2;
            }
        }
        if (threadIdx.x < 32) {
            int c = base + threadIdx.x;
            float inv, sh;
            if (grp < 3) {
                inv = g2[c] * rsqrtf(v2[c] + 1e-5f);
                sh  = b2[c] - m2[c] * inv;
            } else {
                inv = g3[c] * rsqrtf(v3[c] + 1e-5f);
                sh  = b3[c] - m3[c] * inv;
            }
            sw[4 * threadIdx.x + 3] = __float_as_uint(inv);
            ssh[threadIdx.x] = sh;
        }
    } else {
        const int base = (grp - 6) * 32;
#pragma unroll
        for (int o = wrp; o < 32; o += 8) {
            uint32_t p = __ballot_sync(0xffffffffu, w4[(base + o) * 32 + lane] > 0.0f);
            if (lane == 0) sw[4 * o] = p;
        }
        if (threadIdx.x < 32) {
            int c = base + threadIdx.x;
            float inv = g4[c] * rsqrtf(v4[c] + 1e-5f);
            sw[4 * threadIdx.x + 3] = __float_as_uint(inv);
            ssh[threadIdx.x] = b4[c] - m4[c] * inv;
        }
    }
    __syncthreads();

    // ---- pixel group: 4 consecutive pixels along a row
    const int q  = blockIdx.x * 256 + threadIdx.x;  // 0..50175
    const int p  = q * 4;
    const int bb = p / HW;
    const int s  = p - bb * HW;          // multiple of 4
    const int y  = s / WID;
    const int xs = s - y * WID;          // 0..52, multiple of 4

    uint4 C = *(const uint4*)&g_a[p];
    int pc0 = __popc(C.x), pc1 = __popc(C.y), pc2 = __popc(C.z), pc3 = __popc(C.w);

    float* ob = out + (size_t)bb * 256 * HW + s;

    if (grp < 3) {
        // ---- Branch V: 3x1 vertical conv
        uint4 U = make_uint4(0, 0, 0, 0), D = make_uint4(0, 0, 0, 0);
        if (y > 0)  U = *(const uint4*)&g_a[p - WID];
        if (y < 55) D = *(const uint4*)&g_a[p + WID];
        int pv0 = __popc(U.x) + pc0 + __popc(D.x);
        int pv1 = __popc(U.y) + pc1 + __popc(D.y);
        int pv2 = __popc(U.z) + pc2 + __popc(D.z);
        int pv3 = __popc(U.w) + pc3 + __popc(D.w);

        float* o1 = ob + (size_t)(grp * 32) * HW;
#pragma unroll 4
        for (int o = 0; o < 32; o++) {
            uint4 wv = *(const uint4*)&sw[4 * o];
            float inv = __uint_as_float(wv.w);
            float sh  = ssh[o];
            float4 rv;
            int d;
            d = 2 * (__popc(U.x & wv.x) + __popc(C.x & wv.y) + __popc(D.x & wv.z)) - pv0;
            rv.x = fmaxf(fmaf((float)d, inv, sh), 0.0f);
            d = 2 * (__popc(U.y & wv.x) + __popc(C.y & wv.y) + __popc(D.y & wv.z)) - pv1;
            rv.y = fmaxf(fmaf((float)d, inv, sh), 0.0f);
            d = 2 * (__popc(U.z & wv.x) + __popc(C.z & wv.y) + __popc(D.z & wv.z)) - pv2;
            rv.z = fmaxf(fmaf((float)d, inv, sh), 0.0f);
            d = 2 * (__popc(U.w & wv.x) + __popc(C.w & wv.y) + __popc(D.w & wv.z)) - pv3;
            rv.w = fmaxf(fmaf((float)d, inv, sh), 0.0f);
            *(float4*)(o1 + (size_t)o * HW) = rv;
        }
    } else if (grp < 6) {
        // ---- Branch H: 1x3 horizontal conv
        uint32_t hL = (xs > 0)  ? g_a[p - 1] : 0u;
        uint32_t hR = (xs < 52) ? g_a[p + 4] : 0u;
        int pL = __popc(hL), pR = __popc(hR);
        int ph0 = pL  + pc0 + pc1;
        int ph1 = pc0 + pc1 + pc2;
        int ph2 = pc1 + pc2 + pc3;
        int ph3 = pc2 + pc3 + pR;

        float* o2 = ob + (size_t)(96 + (grp - 3) * 32) * HW;
#pragma unroll 4
        for (int o = 0; o < 32; o++) {
            uint4 wv = *(const uint4*)&sw[4 * o];
            float inv = __uint_as_float(wv.w);
            float sh  = ssh[o];
            float4 rv;
            int d;
            d = 2 * (__popc(hL  & wv.x) + __popc(C.x & wv.y) + __popc(C.y & wv.z)) - ph0;
            rv.x = fmaxf(fmaf((float)d, inv, sh), 0.0f);
            d = 2 * (__popc(C.x & wv.x) + __popc(C.y & wv.y) + __popc(C.z & wv.z)) - ph1;
            rv.y = fmaxf(fmaf((float)d, inv, sh), 0.0f);
            d = 2 * (__popc(C.y & wv.x) + __popc(C.z & wv.y) + __popc(C.w & wv.z)) - ph2;
            rv.z = fmaxf(fmaf((float)d, inv, sh), 0.0f);
            d = 2 * (__popc(C.z & wv.x) + __popc(C.w & wv.y) + __popc(hR  & wv.z)) - ph3;
            rv.w = fmaxf(fmaf((float)d, inv, sh), 0.0f);
            *(float4*)(o2 + (size_t)o * HW) = rv;
        }
    } else {
        // ---- Branch P: 1x1 conv
        float* o3 = ob + (size_t)(192 + (grp - 6) * 32) * HW;
#pragma unroll 4
        for (int o = 0; o < 32; o++) {
            uint4 wv = *(const uint4*)&sw[4 * o];
            float inv = __uint_as_float(wv.w);
            float sh  = ssh[o];
            float4 rv;
            rv.x = fmaxf(fmaf((float)(2 * __popc(C.x & wv.x) - pc0), inv, sh), 0.0f);
            rv.y = fmaxf(fmaf((float)(2 * __popc(C.y & wv.x) - pc1), inv, sh), 0.0f);
            rv.z = fmaxf(fmaf((float)(2 * __popc(C.z & wv.x) - pc2), inv, sh), 0.0f);
            rv.w = fmaxf(fmaf((float)(2 * __popc(C.w & wv.x) - pc3), inv, sh), 0.0f);
            *(float4*)(o3 + (size_t)o * HW) = rv;
        }
    }
}

// ---------------------------------------------------------------------------
extern "C" void kernel_launch(void* const* d_in, const int* in_sizes, int n_in,
                              void* d_out, int out_size)
{
    const float* x = (const float*)d_in[0];
    kA<<<NTHR4 / 256, 256>>>(x,
                             (const float*)d_in[1], (const float*)d_in[2],
                             (const float*)d_in[3], (const float*)d_in[4],
                             (const float*)d_in[5]);
    dim3 gridB(NTHR4 / 256, 8);
    kB<<<gridB, 256>>>(
        (const float*)d_in[6],  (const float*)d_in[7],
        (const float*)d_in[8],  (const float*)d_in[9],
        (const float*)d_in[10],
        (const float*)d_in[11], (const float*)d_in[12],
        (const float*)d_in[13], (const float*)d_in[14],
        (const float*)d_in[15],
        (const float*)d_in[16], (const float*)d_in[17],
        (const float*)d_in[18], (const float*)d_in[19],
        (const float*)d_in[20],
        (float*)d_out);
}

// round 8
// speedup vs baseline: 1.7372x; 1.0483x over previous
#include <cuda_runtime.h>
#include <stdint.h>

#define NPIX  200704        // 64 * 56 * 56
#define HW    3136          // 56 * 56
#define WID   56
#define NTHR4 (NPIX / 4)    // kB pixel threads: 50176, 4 px each
#define NTHR2 (NPIX / 2)    // kA threads: 100352, 2 px each

// Intermediate: 32 sign bits (channels of h) per pixel, layout [b*HW + s]
__device__ uint32_t g_a[NPIX];

// ---------------------------------------------------------------------------
// Kernel A: x [N=64, C=64, 56, 56] (NCHW) -> g_a sign masks.
// Self-contained: packs w1 + folds BN1 per block (ballot), then 2 px/thread.
// ---------------------------------------------------------------------------
__global__ __launch_bounds__(256) void kA(const float* __restrict__ x,
                                          const float* __restrict__ w1,
                                          const float* __restrict__ g1,
                                          const float* __restrict__ b1,
                                          const float* __restrict__ m1,
                                          const float* __restrict__ v1)
{
    __shared__ unsigned long long sw1[32];
    __shared__ float sinv[32], ssh[32];

    const int wid8 = threadIdx.x >> 5;
    const int lane = threadIdx.x & 31;

#pragma unroll
    for (int o = wid8; o < 32; o += 8) {
        float lo = w1[o * 64 + lane];
        float hi = w1[o * 64 + 32 + lane];
        uint32_t blo = __ballot_sync(0xffffffffu, lo > 0.0f);
        uint32_t bhi = __ballot_sync(0xffffffffu, hi > 0.0f);
        if (lane == 0)
            sw1[o] = (unsigned long long)blo | ((unsigned long long)bhi << 32);
    }
    if (threadIdx.x < 32) {
        int o = threadIdx.x;
        float inv = g1[o] * rsqrtf(v1[o] + 1e-5f);
        sinv[o] = inv;
        ssh[o]  = b1[o] - m1[o] * inv;
    }
    __syncthreads();

    int t = blockIdx.x * 256 + threadIdx.x;
    if (t >= NTHR2) return;
    int p = t * 2;                 // global pixel index = b*HW + s
    int b = p / HW;
    int s = p - b * HW;            // even
    const float* xb = x + (size_t)b * 64 * HW + s;

    unsigned long long xb0 = 0, xb1 = 0;
#pragma unroll
    for (int c = 0; c < 64; c++) {
        float2 v = __ldg((const float2*)(xb + (size_t)c * HW));
        unsigned long long m = 1ull << c;
        if (v.x > 0.0f) xb0 |= m;
        if (v.y > 0.0f) xb1 |= m;
    }

    uint32_t a0 = 0, a1 = 0;
#pragma unroll
    for (int o = 0; o < 32; o++) {
        unsigned long long wb = sw1[o];
        float inv = sinv[o], sh = ssh[o];
        uint32_t m = 1u << o;
        int d0 = 64 - 2 * __popcll(xb0 ^ wb);
        int d1 = 64 - 2 * __popcll(xb1 ^ wb);
        if (fmaf((float)d0, inv, sh) > 0.0f) a0 |= m;
        if (fmaf((float)d1, inv, sh) > 0.0f) a1 |= m;
    }
    *(uint2*)(g_a + p) = make_uint2(a0, a1);
}

// ---------------------------------------------------------------------------
// Kernel B: g_a -> output [64,256,56,56].
// Grid (196, 8): blockIdx.x = pixel tile (256 threads x 4 px),
// blockIdx.y = 32-channel group: 0-2 = branch V (w2), 3-5 = branch H (w3),
// 6-7 = branch P (w4). Per-block ballot prep of just its 32 channels.
// ---------------------------------------------------------------------------
__global__ __launch_bounds__(256) void kB(
    const float* __restrict__ w2, const float* __restrict__ g2,
    const float* __restrict__ b2, const float* __restrict__ m2,
    const float* __restrict__ v2,
    const float* __restrict__ w3, const float* __restrict__ g3,
    const float* __restrict__ b3, const float* __restrict__ m3,
    const float* __restrict__ v3,
    const float* __restrict__ w4, const float* __restrict__ g4,
    const float* __restrict__ b4, const float* __restrict__ m4,
    const float* __restrict__ v4,
    float* __restrict__ out)
{
    __shared__ __align__(16) uint32_t sw[32 * 4];
    __shared__ float ssh[32];

    const int grp  = blockIdx.y;        // 0..7
    const int wrp  = threadIdx.x >> 5;  // 0..7
    const int lane = threadIdx.x & 31;

    // ---- per-block prep: 32 channels only
    if (grp < 6) {
        const float* wsrc = (grp < 3) ? w2 : w3;
        const int base = (grp < 3 ? grp : grp - 3) * 32;
#pragma unroll
        for (int o = wrp; o < 32; o += 8) {
            const float* pw = wsrc + ((base + o) * 32 + lane) * 3;
            float a0 = pw[0], a1 = pw[1], a2 = pw[2];
            uint32_t x0 = __ballot_sync(0xffffffffu, a0 > 0.0f);
            uint32_t x1 = __ballot_sync(0xffffffffu, a1 > 0.0f);
            uint32_t x2 = __ballot_sync(0xffffffffu, a2 > 0.0f);
            if (lane == 0) {
                sw[4 * o] = x0; sw[4 * o + 1] = x1; sw[4 * o + 2] = x2;
            }
        }
        if (threadIdx.x < 32) {
            int c = base + threadIdx.x;
            float inv, sh;
            if (grp < 3) {
                inv = g2[c] * rsqrtf(v2[c] + 1e-5f);
                sh  = b2[c] - m2[c] * inv;
            } else {
                inv = g3[c] * rsqrtf(v3[c] + 1e-5f);
                sh  = b3[c] - m3[c] * inv;
            }
            sw[4 * threadIdx.x + 3] = __float_as_uint(inv);
            ssh[threadIdx.x] = sh;
        }
    } else {
        const int base = (grp - 6) * 32;
#pragma unroll
        for (int o = wrp; o < 32; o += 8) {
            uint32_t p = __ballot_sync(0xffffffffu, w4[(base + o) * 32 + lane] > 0.0f);
            if (lane == 0) sw[4 * o] = p;
        }
        if (threadIdx.x < 32) {
            int c = base + threadIdx.x;
            float inv = g4[c] * rsqrtf(v4[c] + 1e-5f);
            sw[4 * threadIdx.x + 3] = __float_as_uint(inv);
            ssh[threadIdx.x] = b4[c] - m4[c] * inv;
        }
    }
    __syncthreads();

    // ---- pixel group: 4 consecutive pixels along a row
    const int q  = blockIdx.x * 256 + threadIdx.x;  // 0..50175
    const int p  = q * 4;
    const int bb = p / HW;
    const int s  = p - bb * HW;          // multiple of 4
    const int y  = s / WID;
    const int xs = s - y * WID;          // 0..52, multiple of 4

    uint4 C = *(const uint4*)&g_a[p];
    int pc0 = __popc(C.x), pc1 = __popc(C.y), pc2 = __popc(C.z), pc3 = __popc(C.w);

    float* ob = out + (size_t)bb * 256 * HW + s;

    if (grp < 3) {
        // ---- Branch V: 3x1 vertical conv
        uint4 U = make_uint4(0, 0, 0, 0), D = make_uint4(0, 0, 0, 0);
        if (y > 0)  U = *(const uint4*)&g_a[p - WID];
        if (y < 55) D = *(const uint4*)&g_a[p + WID];
        int pv0 = __popc(U.x) + pc0 + __popc(D.x);
        int pv1 = __popc(U.y) + pc1 + __popc(D.y);
        int pv2 = __popc(U.z) + pc2 + __popc(D.z);
        int pv3 = __popc(U.w) + pc3 + __popc(D.w);

        float* o1 = ob + (size_t)(grp * 32) * HW;
#pragma unroll 4
        for (int o = 0; o < 32; o++) {
            uint4 wv = *(const uint4*)&sw[4 * o];
            float inv = __uint_as_float(wv.w);
            float sh  = ssh[o];
            float4 rv;
            int d;
            d = 2 * (__popc(U.x & wv.x) + __popc(C.x & wv.y) + __popc(D.x & wv.z)) - pv0;
            rv.x = fmaxf(fmaf((float)d, inv, sh), 0.0f);
            d = 2 * (__popc(U.y & wv.x) + __popc(C.y & wv.y) + __popc(D.y & wv.z)) - pv1;
            rv.y = fmaxf(fmaf((float)d, inv, sh), 0.0f);
            d = 2 * (__popc(U.z & wv.x) + __popc(C.z & wv.y) + __popc(D.z & wv.z)) - pv2;
            rv.z = fmaxf(fmaf((float)d, inv, sh), 0.0f);
            d = 2 * (__popc(U.w & wv.x) + __popc(C.w & wv.y) + __popc(D.w & wv.z)) - pv3;
            rv.w = fmaxf(fmaf((float)d, inv, sh), 0.0f);
            *(float4*)(o1 + (size_t)o * HW) = rv;
        }
    } else if (grp < 6) {
        // ---- Branch H: 1x3 horizontal conv
        uint32_t hL = (xs > 0)  ? g_a[p - 1] : 0u;
        uint32_t hR = (xs < 52) ? g_a[p + 4] : 0u;
        int pL = __popc(hL), pR = __popc(hR);
        int ph0 = pL  + pc0 + pc1;
        int ph1 = pc0 + pc1 + pc2;
        int ph2 = pc1 + pc2 + pc3;
        int ph3 = pc2 + pc3 + pR;

        float* o2 = ob + (size_t)(96 + (grp - 3) * 32) * HW;
#pragma unroll 4
        for (int o = 0; o < 32; o++) {
            uint4 wv = *(const uint4*)&sw[4 * o];
            float inv = __uint_as_float(wv.w);
            float sh  = ssh[o];
            float4 rv;
            int d;
            d = 2 * (__popc(hL  & wv.x) + __popc(C.x & wv.y) + __popc(C.y & wv.z)) - ph0;
            rv.x = fmaxf(fmaf((float)d, inv, sh), 0.0f);
            d = 2 * (__popc(C.x & wv.x) + __popc(C.y & wv.y) + __popc(C.z & wv.z)) - ph1;
            rv.y = fmaxf(fmaf((float)d, inv, sh), 0.0f);
            d = 2 * (__popc(C.y & wv.x) + __popc(C.z & wv.y) + __popc(C.w & wv.z)) - ph2;
            rv.z = fmaxf(fmaf((float)d, inv, sh), 0.0f);
            d = 2 * (__popc(C.z & wv.x) + __popc(C.w & wv.y) + __popc(hR  & wv.z)) - ph3;
            rv.w = fmaxf(fmaf((float)d, inv, sh), 0.0f);
            *(float4*)(o2 + (size_t)o * HW) = rv;
        }
    } else {
        // ---- Branch P: 1x1 conv
        float* o3 = ob + (size_t)(192 + (grp - 6) * 32) * HW;
#pragma unroll 4
        for (int o = 0; o < 32; o++) {
            uint4 wv = *(const uint4*)&sw[4 * o];
            float inv = __uint_as_float(wv.w);
            float sh  = ssh[o];
            float4 rv;
            rv.x = fmaxf(fmaf((float)(2 * __popc(C.x & wv.x) - pc0), inv, sh), 0.0f);
            rv.y = fmaxf(fmaf((float)(2 * __popc(C.y & wv.x) - pc1), inv, sh), 0.0f);
            rv.z = fmaxf(fmaf((float)(2 * __popc(C.z & wv.x) - pc2), inv, sh), 0.0f);
            rv.w = fmaxf(fmaf((float)(2 * __popc(C.w & wv.x) - pc3), inv, sh), 0.0f);
            *(float4*)(o3 + (size_t)o * HW) = rv;
        }
    }
}

// ---------------------------------------------------------------------------
extern "C" void kernel_launch(void* const* d_in, const int* in_sizes, int n_in,
                              void* d_out, int out_size)
{
    const float* x = (const float*)d_in[0];
    kA<<<NTHR2 / 256, 256>>>(x,
                             (const float*)d_in[1], (const float*)d_in[2],
                             (const float*)d_in[3], (const float*)d_in[4],
                             (const float*)d_in[5]);
    dim3 gridB(NTHR4 / 256, 8);
    kB<<<gridB, 256>>>(
        (const float*)d_in[6],  (const float*)d_in[7],
        (const float*)d_in[8],  (const float*)d_in[9],
        (const float*)d_in[10],
        (const float*)d_in[11], (const float*)d_in[12],
        (const float*)d_in[13], (const float*)d_in[14],
        (const float*)d_in[15],
        (const float*)d_in[16], (const float*)d_in[17],
        (const float*)d_in[18], (const float*)d_in[19],
        (const float*)d_in[20],
        (float*)d_out);
}

// round 9
// speedup vs baseline: 1.7729x; 1.0205x over previous
#include <cuda_runtime.h>
#include <stdint.h>

#define NPIX  200704        // 64 * 56 * 56
#define HW    3136          // 56 * 56
#define WID   56
#define NTHR4 (NPIX / 4)    // kB pixel threads: 50176, 4 px each

// Intermediate: 32 sign bits (channels of h) per pixel, layout [b*HW + s]
__device__ uint32_t g_a[NPIX];

// ---------------------------------------------------------------------------
// Kernel A: x [N=64, C=64, 56, 56] (NCHW) -> g_a sign masks.
// Self-contained: packs w1 + folds BN1 per block (ballot), then 1 px/thread.
// 784 blocks -> ~42 resident warps/SM for latency hiding.
// ---------------------------------------------------------------------------
__global__ __launch_bounds__(256) void kA(const float* __restrict__ x,
                                          const float* __restrict__ w1,
                                          const float* __restrict__ g1,
                                          const float* __restrict__ b1,
                                          const float* __restrict__ m1,
                                          const float* __restrict__ v1)
{
    __shared__ unsigned long long sw1[32];
    __shared__ float sinv[32], ssh[32];

    const int wid8 = threadIdx.x >> 5;
    const int lane = threadIdx.x & 31;

#pragma unroll
    for (int o = wid8; o < 32; o += 8) {
        float lo = w1[o * 64 + lane];
        float hi = w1[o * 64 + 32 + lane];
        uint32_t blo = __ballot_sync(0xffffffffu, lo > 0.0f);
        uint32_t bhi = __ballot_sync(0xffffffffu, hi > 0.0f);
        if (lane == 0)
            sw1[o] = (unsigned long long)blo | ((unsigned long long)bhi << 32);
    }
    if (threadIdx.x < 32) {
        int o = threadIdx.x;
        float inv = g1[o] * rsqrtf(v1[o] + 1e-5f);
        sinv[o] = inv;
        ssh[o]  = b1[o] - m1[o] * inv;
    }
    __syncthreads();

    int p = blockIdx.x * 256 + threadIdx.x;   // global pixel index = b*HW + s
    if (p >= NPIX) return;
    int b = p / HW;
    int s = p - b * HW;
    const float* xb = x + (size_t)b * 64 * HW + s;

    unsigned long long xbits = 0;
#pragma unroll
    for (int c = 0; c < 64; c++) {
        float v = __ldg(xb + (size_t)c * HW);
        if (v > 0.0f) xbits |= 1ull << c;
    }

    uint32_t a0 = 0;
#pragma unroll
    for (int o = 0; o < 32; o++) {
        unsigned long long wb = sw1[o];
        float inv = sinv[o], sh = ssh[o];
        int d = 64 - 2 * __popcll(xbits ^ wb);
        if (fmaf((float)d, inv, sh) > 0.0f) a0 |= 1u << o;
    }
    g_a[p] = a0;
}

// ---------------------------------------------------------------------------
// Kernel B: g_a -> output [64,256,56,56].
// Grid (196, 8): blockIdx.x = pixel tile (256 threads x 4 px),
// blockIdx.y = 32-channel group: 0-2 = branch V (w2), 3-5 = branch H (w3),
// 6-7 = branch P (w4). Per-block ballot prep of just its 32 channels.
// ---------------------------------------------------------------------------
__global__ __launch_bounds__(256) void kB(
    const float* __restrict__ w2, const float* __restrict__ g2,
    const float* __restrict__ b2, const float* __restrict__ m2,
    const float* __restrict__ v2,
    const float* __restrict__ w3, const float* __restrict__ g3,
    const float* __restrict__ b3, const float* __restrict__ m3,
    const float* __restrict__ v3,
    const float* __restrict__ w4, const float* __restrict__ g4,
    const float* __restrict__ b4, const float* __restrict__ m4,
    const float* __restrict__ v4,
    float* __restrict__ out)
{
    __shared__ __align__(16) uint32_t sw[32 * 4];
    __shared__ float ssh[32];

    const int grp  = blockIdx.y;        // 0..7
    const int wrp  = threadIdx.x >> 5;  // 0..7
    const int lane = threadIdx.x & 31;

    // ---- per-block prep: 32 channels only
    if (grp < 6) {
        const float* wsrc = (grp < 3) ? w2 : w3;
        const int base = (grp < 3 ? grp : grp - 3) * 32;
#pragma unroll
        for (int o = wrp; o < 32; o += 8) {
            const float* pw = wsrc + ((base + o) * 32 + lane) * 3;
            float a0 = pw[0], a1 = pw[1], a2 = pw[2];
            uint32_t x0 = __ballot_sync(0xffffffffu, a0 > 0.0f);
            uint32_t x1 = __ballot_sync(0xffffffffu, a1 > 0.0f);
            uint32_t x2 = __ballot_sync(0xffffffffu, a2 > 0.0f);
            if (lane == 0) {
                sw[4 * o] = x0; sw[4 * o + 1] = x1; sw[4 * o + 2] = x2;
            }
        }
        if (threadIdx.x < 32) {
            int c = base + threadIdx.x;
            float inv, sh;
            if (grp < 3) {
                inv = g2[c] * rsqrtf(v2[c] + 1e-5f);
                sh  = b2[c] - m2[c] * inv;
            } else {
                inv = g3[c] * rsqrtf(v3[c] + 1e-5f);
                sh  = b3[c] - m3[c] * inv;
            }
            sw[4 * threadIdx.x + 3] = __float_as_uint(inv);
            ssh[threadIdx.x] = sh;
        }
    } else {
        const int base = (grp - 6) * 32;
#pragma unroll
        for (int o = wrp; o < 32; o += 8) {
            uint32_t p = __ballot_sync(0xffffffffu, w4[(base + o) * 32 + lane] > 0.0f);
            if (lane == 0) sw[4 * o] = p;
        }
        if (threadIdx.x < 32) {
            int c = base + threadIdx.x;
            float inv = g4[c] * rsqrtf(v4[c] + 1e-5f);
            sw[4 * threadIdx.x + 1] = __float_as_uint(inv);
            sw[4 * threadIdx.x + 2] = __float_as_uint(b4[c] - m4[c] * inv);
        }
    }
    __syncthreads();

    // ---- pixel group: 4 consecutive pixels along a row
    const int q  = blockIdx.x * 256 + threadIdx.x;  // 0..50175
    const int p  = q * 4;
    const int bb = p / HW;
    const int s  = p - bb * HW;          // multiple of 4
    const int y  = s / WID;
    const int xs = s - y * WID;          // 0..52, multiple of 4

    uint4 C = *(const uint4*)&g_a[p];
    int pc0 = __popc(C.x), pc1 = __popc(C.y), pc2 = __popc(C.z), pc3 = __popc(C.w);

    float* ob = out + (size_t)bb * 256 * HW + s;

    if (grp < 3) {
        // ---- Branch V: 3x1 vertical conv
        uint4 U = make_uint4(0, 0, 0, 0), D = make_uint4(0, 0, 0, 0);
        if (y > 0)  U = *(const uint4*)&g_a[p - WID];
        if (y < 55) D = *(const uint4*)&g_a[p + WID];
        int pv0 = __popc(U.x) + pc0 + __popc(D.x);
        int pv1 = __popc(U.y) + pc1 + __popc(D.y);
        int pv2 = __popc(U.z) + pc2 + __popc(D.z);
        int pv3 = __popc(U.w) + pc3 + __popc(D.w);

        float* o1 = ob + (size_t)(grp * 32) * HW;
#pragma unroll 8
        for (int o = 0; o < 32; o++) {
            uint4 wv = *(const uint4*)&sw[4 * o];
            float inv = __uint_as_float(wv.w);
            float sh  = ssh[o];
            float4 rv;
            int d;
            d = 2 * (__popc(U.x & wv.x) + __popc(C.x & wv.y) + __popc(D.x & wv.z)) - pv0;
            rv.x = fmaxf(fmaf((float)d, inv, sh), 0.0f);
            d = 2 * (__popc(U.y & wv.x) + __popc(C.y & wv.y) + __popc(D.y & wv.z)) - pv1;
            rv.y = fmaxf(fmaf((float)d, inv, sh), 0.0f);
            d = 2 * (__popc(U.z & wv.x) + __popc(C.z & wv.y) + __popc(D.z & wv.z)) - pv2;
            rv.z = fmaxf(fmaf((float)d, inv, sh), 0.0f);
            d = 2 * (__popc(U.w & wv.x) + __popc(C.w & wv.y) + __popc(D.w & wv.z)) - pv3;
            rv.w = fmaxf(fmaf((float)d, inv, sh), 0.0f);
            *(float4*)(o1 + (size_t)o * HW) = rv;
        }
    } else if (grp < 6) {
        // ---- Branch H: 1x3 horizontal conv
        uint32_t hL = (xs > 0)  ? g_a[p - 1] : 0u;
        uint32_t hR = (xs < 52) ? g_a[p + 4] : 0u;
        int pL = __popc(hL), pR = __popc(hR);
        int ph0 = pL  + pc0 + pc1;
        int ph1 = pc0 + pc1 + pc2;
        int ph2 = pc1 + pc2 + pc3;
        int ph3 = pc2 + pc3 + pR;

        float* o2 = ob + (size_t)(96 + (grp - 3) * 32) * HW;
#pragma unroll 8
        for (int o = 0; o < 32; o++) {
            uint4 wv = *(const uint4*)&sw[4 * o];
            float inv = __uint_as_float(wv.w);
            float sh  = ssh[o];
            float4 rv;
            int d;
            d = 2 * (__popc(hL  & wv.x) + __popc(C.x & wv.y) + __popc(C.y & wv.z)) - ph0;
            rv.x = fmaxf(fmaf((float)d, inv, sh), 0.0f);
            d = 2 * (__popc(C.x & wv.x) + __popc(C.y & wv.y) + __popc(C.z & wv.z)) - ph1;
            rv.y = fmaxf(fmaf((float)d, inv, sh), 0.0f);
            d = 2 * (__popc(C.y & wv.x) + __popc(C.z & wv.y) + __popc(C.w & wv.z)) - ph2;
            rv.z = fmaxf(fmaf((float)d, inv, sh), 0.0f);
            d = 2 * (__popc(C.z & wv.x) + __popc(C.w & wv.y) + __popc(hR  & wv.z)) - ph3;
            rv.w = fmaxf(fmaf((float)d, inv, sh), 0.0f);
            *(float4*)(o2 + (size_t)o * HW) = rv;
        }
    } else {
        // ---- Branch P: 1x1 conv (sh packed in wv.z — no ssh load)
        float* o3 = ob + (size_t)(192 + (grp - 6) * 32) * HW;
#pragma unroll 8
        for (int o = 0; o < 32; o++) {
            uint4 wv = *(const uint4*)&sw[4 * o];
            float inv = __uint_as_float(wv.y);
            float sh  = __uint_as_float(wv.z);
            float4 rv;
            rv.x = fmaxf(fmaf((float)(2 * __popc(C.x & wv.x) - pc0), inv, sh), 0.0f);
            rv.y = fmaxf(fmaf((float)(2 * __popc(C.y & wv.x) - pc1), inv, sh), 0.0f);
            rv.z = fmaxf(fmaf((float)(2 * __popc(C.z & wv.x) - pc2), inv, sh), 0.0f);
            rv.w = fmaxf(fmaf((float)(2 * __popc(C.w & wv.x) - pc3), inv, sh), 0.0f);
            *(float4*)(o3 + (size_t)o * HW) = rv;
        }
    }
}

// ---------------------------------------------------------------------------
extern "C" void kernel_launch(void* const* d_in, const int* in_sizes, int n_in,
                              void* d_out, int out_size)
{
    const float* x = (const float*)d_in[0];
    kA<<<NPIX / 256, 256>>>(x,
                            (const float*)d_in[1], (const float*)d_in[2],
                            (const float*)d_in[3], (const float*)d_in[4],
                            (const float*)d_in[5]);
    dim3 gridB(NTHR4 / 256, 8);
    kB<<<gridB, 256>>>(
        (const float*)d_in[6],  (const float*)d_in[7],
        (const float*)d_in[8],  (const float*)d_in[9],
        (const float*)d_in[10],
        (const float*)d_in[11], (const float*)d_in[12],
        (const float*)d_in[13], (const float*)d_in[14],
        (const float*)d_in[15],
        (const float*)d_in[16], (const float*)d_in[17],
        (const float*)d_in[18], (const float*)d_in[19],
        (const float*)d_in[20],
        (float*)d_out);
}